// round 8
// baseline (speedup 1.0000x reference)
#include <cuda_runtime.h>
#include <cuda_bf16.h>
#include <cstdint>

// Problem constants
#define BATCH 64
#define CIN   64
#define H     128
#define W     128
#define HW    (H*W)
#define COUT  256
#define OH    126
#define OW    126
#define MTOT  (OH*OW)     // 15876
#define KTOT  (CIN*9)     // 576
#define NSTG  (KTOT/32)   // 18 stages of K=32

static const size_t XN = (size_t)BATCH * CIN * H * W;   // 67,108,864

// Scratch (__device__ globals: allocation-free per harness rules)
// Three copies of x in bf16, shifted left by 0/1/2 elements (kw shift baked in)
__device__ __align__(16) __nv_bfloat16 g_xs[3][(size_t)BATCH*CIN*H*W + 64];
// Weights transposed + K-reordered: g_wbf[k'][co], k' = (kh*3+kw)*64 + ci
__device__ __align__(16) __nv_bfloat16 g_wbf[KTOT*COUT];

// ---------------- prologue kernels ----------------

__device__ __forceinline__ uint32_t packbf(float lo, float hi) {
    __nv_bfloat162 h = __floats2bfloat162_rn(lo, hi);
    return *reinterpret_cast<uint32_t*>(&h);
}

__global__ void cvt_x3_kernel(const float* __restrict__ x) {
    size_t p = ((size_t)blockIdx.x * blockDim.x + threadIdx.x) * 8;
    float4 a = *reinterpret_cast<const float4*>(x + p);
    float4 b = *reinterpret_cast<const float4*>(x + p + 4);
    float cx = 0.f, cy = 0.f;
    if (p + 8 < XN) cx = x[p + 8];
    if (p + 9 < XN) cy = x[p + 9];
    uint32_t r0 = packbf(a.x, a.y);
    uint32_t r1 = packbf(a.z, a.w);
    uint32_t r2 = packbf(b.x, b.y);
    uint32_t r3 = packbf(b.z, b.w);
    uint32_t r4 = packbf(cx, cy);
    *reinterpret_cast<uint4*>(&g_xs[0][p]) = make_uint4(r0, r1, r2, r3);
    uint32_t v0 = __funnelshift_r(r0, r1, 16);
    uint32_t v1 = __funnelshift_r(r1, r2, 16);
    uint32_t v2 = __funnelshift_r(r2, r3, 16);
    uint32_t v3 = __funnelshift_r(r3, r4, 16);
    *reinterpret_cast<uint4*>(&g_xs[1][p]) = make_uint4(v0, v1, v2, v3);
    *reinterpret_cast<uint4*>(&g_xs[2][p]) = make_uint4(r1, r2, r3, r4);
}

__global__ void cvt_w_kernel(const float* __restrict__ w) {
    // k' = khw*64 + ci ; original k = ci*9 + khw
    int kp = blockIdx.x;       // 0..575
    int n  = threadIdx.x;      // 0..255
    int ci  = kp & 63;
    int khw = kp >> 6;
    g_wbf[kp * COUT + n] = __float2bfloat16(w[n * KTOT + ci * 9 + khw]);
}

__global__ void zero_kernel(float* out) {
    out[blockIdx.x * blockDim.x + threadIdx.x] = 0.0f;
}

// ---------------- main implicit-GEMM kernel ----------------

#define PM 136     // A smem pitch (272B rows, conflict-free trans ldmatrix)
#define PN 264     // B smem pitch (528B rows)
#define STG 4
#define ASTG (32 * PM * 2)   // 8704 B per stage
#define BSTG (32 * PN * 2)   // 16896 B per stage

__device__ __forceinline__ uint32_t smem_u32(const void* p) {
    return (uint32_t)__cvta_generic_to_shared(p);
}

__device__ __forceinline__ void cp16(uint32_t dst, const void* src) {
    asm volatile("cp.async.cg.shared.global [%0], [%1], 16;\n" :: "r"(dst), "l"(src));
}

__device__ __forceinline__ void ldsm4t(uint32_t& r0, uint32_t& r1, uint32_t& r2,
                                       uint32_t& r3, uint32_t addr) {
    asm volatile("ldmatrix.sync.aligned.m8n8.x4.trans.shared.b16 {%0,%1,%2,%3}, [%4];"
                 : "=r"(r0), "=r"(r1), "=r"(r2), "=r"(r3) : "r"(addr));
}

__device__ __forceinline__ void mma16816(float c[4],
                                         uint32_t a0, uint32_t a1, uint32_t a2, uint32_t a3,
                                         uint32_t b0, uint32_t b1) {
    asm volatile("mma.sync.aligned.m16n8k16.row.col.f32.bf16.bf16.f32 "
                 "{%0,%1,%2,%3}, {%4,%5,%6,%7}, {%8,%9}, {%0,%1,%2,%3};"
                 : "+f"(c[0]), "+f"(c[1]), "+f"(c[2]), "+f"(c[3])
                 : "r"(a0), "r"(a1), "r"(a2), "r"(a3), "r"(b0), "r"(b1));
}

__device__ __forceinline__ float gelu_tanh(float x) {
    float x3 = x * x * x;
    float u = 0.7978845608028654f * fmaf(0.044715f, x3, x);
    float t;
    asm("tanh.approx.f32 %0, %1;" : "=f"(t) : "f"(u));
    return 0.5f * x * (1.0f + t);
}

__global__ void __launch_bounds__(256, 1)
conv_gemm_kernel(const float* __restrict__ bias, float* __restrict__ out) {
    extern __shared__ char dsm[];
    // Layout: A stages [STG][32*PM], then B stages [STG][32*PN]
    const uint32_t Abase = smem_u32(dsm);
    const uint32_t Bbase = Abase + STG * ASTG;

    const int tid    = threadIdx.x;
    const int lane   = tid & 31;
    const int warp   = tid >> 5;
    const int warp_m = warp >> 2;    // 0..1 -> 64 m-rows each
    const int warp_n = warp & 3;     // 0..3 -> 64 n-cols each
    const int oh = blockIdx.x;       // one output row per CTA
    const int b  = blockIdx.y;

    // staging roles
    const int ak = tid >> 4, aj = tid & 15;   // A: 16 k-rows x 16 chunks per shot
    const int bk = tid >> 5, bj = tid & 31;   // B: 8 k-rows x 32 chunks per shot

    const size_t xrow = ((size_t)(b * CIN)) * HW + (size_t)oh * W;
    const __nv_bfloat16* wsrc = g_wbf + bk * COUT + bj * 8;
    const uint32_t a_sdst = Abase + (ak * PM + aj * 8) * 2;
    const uint32_t b_sdst = Bbase + (bk * PN + bj * 8) * 2;

    // --- pipeline issue: one stage = K32 = two k16 chunks ---
    auto issue = [&](int st) {
        const int slot = st & (STG - 1);
        // A: two shots, shot i covers k-rows [16i,16i+16) = k16 chunk kt=2st+i
        #pragma unroll
        for (int i = 0; i < 2; i++) {
            const int kt  = st * 2 + i;
            const int khw = kt >> 2;
            const int kh  = (khw * 11) >> 5;     // floor(khw/3), khw in [0,9)
            const int kw  = khw - kh * 3;
            const int ci0 = (kt & 3) * 16;
            const __nv_bfloat16* src =
                g_xs[kw] + xrow + (size_t)(ci0 + ak) * HW + kh * W + aj * 8;
            cp16(a_sdst + slot * ASTG + i * (16 * PM * 2), src);
        }
        // B: four shots, shot i covers k-rows [8i, 8i+8); g_wbf rows linear in k'
        #pragma unroll
        for (int i = 0; i < 4; i++) {
            cp16(b_sdst + slot * BSTG + i * (8 * PN * 2),
                 wsrc + (size_t)(st * 32 + i * 8) * COUT);
        }
        asm volatile("cp.async.commit_group;" ::: "memory");
    };

    issue(0); issue(1); issue(2);

    float acc[4][8][4];
    #pragma unroll
    for (int a = 0; a < 4; a++)
        #pragma unroll
        for (int c = 0; c < 8; c++)
            #pragma unroll
            for (int d = 0; d < 4; d++) acc[a][c][d] = 0.0f;

    // ldmatrix lane addressing (constant per lane)
    const int a_krow = (lane & 7) + ((lane & 16) >> 1);
    const int a_moff = warp_m * 64 + (lane & 8);
    const int b_krow = (lane & 7) + (lane & 8);
    const int b_noff = warp_n * 64 + ((lane & 16) >> 1);

    for (int st = 0; st < NSTG; st++) {
        if (st <= NSTG - 3)      asm volatile("cp.async.wait_group 2;" ::: "memory");
        else if (st == NSTG - 2) asm volatile("cp.async.wait_group 1;" ::: "memory");
        else                     asm volatile("cp.async.wait_group 0;" ::: "memory");
        __syncthreads();
        // Writer slot (st+3)&3 != reader slot st&3 with STG=4: no aliasing.
        if (st + 3 < NSTG) issue(st + 3);

        const int slot = st & (STG - 1);
        const uint32_t a_base = Abase + slot * ASTG;
        const uint32_t b_base = Bbase + slot * BSTG;

        uint32_t afr[2][4][4];
        uint32_t bfr[2][8][2];
        // load fragments for both k16 slices up front
        #pragma unroll
        for (int sl = 0; sl < 2; sl++) {
            #pragma unroll
            for (int mi = 0; mi < 4; mi++) {
                uint32_t addr = a_base +
                    (uint32_t)(((sl * 16 + a_krow) * PM + a_moff + mi * 16) * 2);
                ldsm4t(afr[sl][mi][0], afr[sl][mi][1], afr[sl][mi][2], afr[sl][mi][3], addr);
            }
            #pragma unroll
            for (int q = 0; q < 4; q++) {
                uint32_t addr = b_base +
                    (uint32_t)(((sl * 16 + b_krow) * PN + b_noff + q * 16) * 2);
                ldsm4t(bfr[sl][2*q][0], bfr[sl][2*q][1],
                       bfr[sl][2*q+1][0], bfr[sl][2*q+1][1], addr);
            }
        }
        #pragma unroll
        for (int sl = 0; sl < 2; sl++)
            #pragma unroll
            for (int mi = 0; mi < 4; mi++)
                #pragma unroll
                for (int ni = 0; ni < 8; ni++)
                    mma16816(acc[mi][ni],
                             afr[sl][mi][0], afr[sl][mi][1], afr[sl][mi][2], afr[sl][mi][3],
                             bfr[sl][ni][0], bfr[sl][ni][1]);
    }

    // ---- epilogue: bias + GELU + row-mean partial reduction ----
    const int group = lane >> 2;
    const int tid4  = lane & 3;

    float bcol[16];
    #pragma unroll
    for (int j = 0; j < 16; j++) {
        int ni = j >> 1, bs = j & 1;
        bcol[j] = bias[warp_n * 64 + ni * 8 + tid4 * 2 + bs];
    }

    float csum[16];
    #pragma unroll
    for (int j = 0; j < 16; j++) csum[j] = 0.0f;

    #pragma unroll
    for (int mi = 0; mi < 4; mi++) {
        #pragma unroll
        for (int half = 0; half < 2; half++) {
            int ow = warp_m * 64 + mi * 16 + half * 8 + group;
            bool ok = (ow < OW);
            #pragma unroll
            for (int ni = 0; ni < 8; ni++) {
                #pragma unroll
                for (int bs = 0; bs < 2; bs++) {
                    if (ok) {
                        float y = acc[mi][ni][half * 2 + bs] + bcol[ni * 2 + bs];
                        csum[ni * 2 + bs] += gelu_tanh(y);
                    }
                }
            }
        }
    }

    // reduce over the 8 lane-groups holding the same columns
    #pragma unroll
    for (int j = 0; j < 16; j++) {
        csum[j] += __shfl_xor_sync(0xffffffffu, csum[j], 16);
        csum[j] += __shfl_xor_sync(0xffffffffu, csum[j], 8);
        csum[j] += __shfl_xor_sync(0xffffffffu, csum[j], 4);
    }

    if (lane < 4) {
        const float inv = 1.0f / (float)MTOT;
        #pragma unroll
        for (int j = 0; j < 16; j++) {
            int ni = j >> 1, bs = j & 1;
            int n = warp_n * 64 + ni * 8 + tid4 * 2 + bs;
            atomicAdd(&out[b * COUT + n], csum[j] * inv);
        }
    }
}

// ---------------- launch ----------------

#define DSMEM_BYTES (STG * (ASTG + BSTG))   // 102400

extern "C" void kernel_launch(void* const* d_in, const int* in_sizes, int n_in,
                              void* d_out, int out_size) {
    const float* x    = (const float*)d_in[0];   // [64,64,128,128]
    const float* w    = (const float*)d_in[1];   // [256,64,3,3]
    const float* bias = (const float*)d_in[2];   // [256]
    float* out = (float*)d_out;                  // [64,256]

    cudaFuncSetAttribute(conv_gemm_kernel,
                         cudaFuncAttributeMaxDynamicSharedMemorySize, DSMEM_BYTES);

    // 1) x -> bf16, three kw-shifted aligned copies
    cvt_x3_kernel<<<32768, 256>>>(x);
    // 2) weights -> bf16, K-reordered [k'][co]
    cvt_w_kernel<<<KTOT, COUT>>>(w);
    // 3) zero output accumulator
    zero_kernel<<<(BATCH * COUT) / 256, 256>>>(out);
    // 4) fused implicit-GEMM conv + bias + GELU + mean-pool
    dim3 grid(OH, BATCH);    // (126, 64)
    conv_gemm_kernel<<<grid, 256, DSMEM_BYTES>>>(bias, out);
}

// round 9
// speedup vs baseline: 1.1659x; 1.1659x over previous
#include <cuda_runtime.h>
#include <cuda_bf16.h>
#include <cstdint>

// Problem constants
#define BATCH 64
#define CIN   64
#define H     128
#define W     128
#define HW    (H*W)
#define COUT  256
#define OH    126
#define OW    126
#define MTOT  (OH*OW)     // 15876
#define KTOT  (CIN*9)     // 576
#define NSTG  (KTOT/32)   // 18 stages of K=32

static const size_t XN = (size_t)BATCH * CIN * H * W;   // 67,108,864

// Scratch (__device__ globals: allocation-free per harness rules)
// Three copies of x in bf16, shifted left by 0/1/2 elements (kw shift baked in)
__device__ __align__(16) __nv_bfloat16 g_xs[3][(size_t)BATCH*CIN*H*W + 64];
// Weights transposed + K-reordered: g_wbf[k'][co], k' = (kh*3+kw)*64 + ci
__device__ __align__(16) __nv_bfloat16 g_wbf[KTOT*COUT];

// ---------------- prologue kernels ----------------

__device__ __forceinline__ uint32_t packbf(float lo, float hi) {
    __nv_bfloat162 h = __floats2bfloat162_rn(lo, hi);
    return *reinterpret_cast<uint32_t*>(&h);
}

__global__ void cvt_x3_kernel(const float* __restrict__ x) {
    size_t p = ((size_t)blockIdx.x * blockDim.x + threadIdx.x) * 8;
    float4 a = *reinterpret_cast<const float4*>(x + p);
    float4 b = *reinterpret_cast<const float4*>(x + p + 4);
    float cx = 0.f, cy = 0.f;
    if (p + 8 < XN) cx = x[p + 8];
    if (p + 9 < XN) cy = x[p + 9];
    uint32_t r0 = packbf(a.x, a.y);
    uint32_t r1 = packbf(a.z, a.w);
    uint32_t r2 = packbf(b.x, b.y);
    uint32_t r3 = packbf(b.z, b.w);
    uint32_t r4 = packbf(cx, cy);
    *reinterpret_cast<uint4*>(&g_xs[0][p]) = make_uint4(r0, r1, r2, r3);
    uint32_t v0 = __funnelshift_r(r0, r1, 16);
    uint32_t v1 = __funnelshift_r(r1, r2, 16);
    uint32_t v2 = __funnelshift_r(r2, r3, 16);
    uint32_t v3 = __funnelshift_r(r3, r4, 16);
    *reinterpret_cast<uint4*>(&g_xs[1][p]) = make_uint4(v0, v1, v2, v3);
    *reinterpret_cast<uint4*>(&g_xs[2][p]) = make_uint4(r1, r2, r3, r4);
}

__global__ void cvt_w_kernel(const float* __restrict__ w) {
    // k' = khw*64 + ci ; original k = ci*9 + khw
    int kp = blockIdx.x;       // 0..575
    int n  = threadIdx.x;      // 0..255
    int ci  = kp & 63;
    int khw = kp >> 6;
    g_wbf[kp * COUT + n] = __float2bfloat16(w[n * KTOT + ci * 9 + khw]);
}

__global__ void zero_kernel(float* out) {
    out[blockIdx.x * blockDim.x + threadIdx.x] = 0.0f;
}

// ---------------- main implicit-GEMM kernel ----------------
// CTA tile: M128 (one oh row) x N128 (half of COUT); 8 warps, warp tile 64x32.
// 2 CTAs per SM (launch_bounds(256,2)): independent barriers decorrelate stalls.

#define PM 136     // A smem pitch (272B rows, conflict-free trans ldmatrix)
#define PN 136     // B smem pitch (N=128 tile)
#define STG 4
#define ASTG (32 * PM * 2)   // 8704 B per stage
#define BSTG (32 * PN * 2)   // 8704 B per stage

__device__ __forceinline__ uint32_t smem_u32(const void* p) {
    return (uint32_t)__cvta_generic_to_shared(p);
}

__device__ __forceinline__ void cp16(uint32_t dst, const void* src) {
    asm volatile("cp.async.cg.shared.global [%0], [%1], 16;\n" :: "r"(dst), "l"(src));
}

__device__ __forceinline__ void ldsm4t(uint32_t& r0, uint32_t& r1, uint32_t& r2,
                                       uint32_t& r3, uint32_t addr) {
    asm volatile("ldmatrix.sync.aligned.m8n8.x4.trans.shared.b16 {%0,%1,%2,%3}, [%4];"
                 : "=r"(r0), "=r"(r1), "=r"(r2), "=r"(r3) : "r"(addr));
}

__device__ __forceinline__ void mma16816(float c[4],
                                         uint32_t a0, uint32_t a1, uint32_t a2, uint32_t a3,
                                         uint32_t b0, uint32_t b1) {
    asm volatile("mma.sync.aligned.m16n8k16.row.col.f32.bf16.bf16.f32 "
                 "{%0,%1,%2,%3}, {%4,%5,%6,%7}, {%8,%9}, {%0,%1,%2,%3};"
                 : "+f"(c[0]), "+f"(c[1]), "+f"(c[2]), "+f"(c[3])
                 : "r"(a0), "r"(a1), "r"(a2), "r"(a3), "r"(b0), "r"(b1));
}

__device__ __forceinline__ float gelu_tanh(float x) {
    float x3 = x * x * x;
    float u = 0.7978845608028654f * fmaf(0.044715f, x3, x);
    float t;
    asm("tanh.approx.f32 %0, %1;" : "=f"(t) : "f"(u));
    return 0.5f * x * (1.0f + t);
}

__global__ void __launch_bounds__(256, 2)
conv_gemm_kernel(const float* __restrict__ bias, float* __restrict__ out) {
    extern __shared__ char dsm[];
    // Layout: A stages [STG][32*PM], then B stages [STG][32*PN]
    const uint32_t Abase = smem_u32(dsm);
    const uint32_t Bbase = Abase + STG * ASTG;

    const int tid    = threadIdx.x;
    const int lane   = tid & 31;
    const int warp   = tid >> 5;
    const int warp_m = warp >> 2;    // 0..1 -> 64 m-rows each
    const int warp_n = warp & 3;     // 0..3 -> 32 n-cols each
    const int oh = blockIdx.x;       // one output row per CTA
    const int n0 = blockIdx.y * 128; // COUT half
    const int b  = blockIdx.z;

    // staging roles: per k16 sub-chunk, 16 k-rows x 16 chunks of 16B; 1 cp16/thread
    const int sk = tid >> 4, sj = tid & 15;

    const size_t xrow = ((size_t)(b * CIN)) * HW + (size_t)oh * W;
    const __nv_bfloat16* wsrc = g_wbf + n0 + sj * 8;   // + k'*COUT
    const uint32_t a_sdst = Abase + (sk * PM + sj * 8) * 2;
    const uint32_t b_sdst = Bbase + (sk * PN + sj * 8) * 2;

    // --- pipeline issue: one stage = K32 = two k16 chunks ---
    auto issue = [&](int st) {
        const int slot = st & (STG - 1);
        #pragma unroll
        for (int i = 0; i < 2; i++) {
            const int kt  = st * 2 + i;
            const int khw = kt >> 2;
            const int kh  = (khw * 11) >> 5;     // floor(khw/3), khw in [0,9)
            const int kw  = khw - kh * 3;
            const int ci0 = (kt & 3) * 16;
            const __nv_bfloat16* asrc =
                g_xs[kw] + xrow + (size_t)(ci0 + sk) * HW + kh * W + sj * 8;
            cp16(a_sdst + slot * ASTG + i * (16 * PM * 2), asrc);
            cp16(b_sdst + slot * BSTG + i * (16 * PN * 2),
                 wsrc + (size_t)(kt * 16 + sk) * COUT);
        }
        asm volatile("cp.async.commit_group;" ::: "memory");
    };

    issue(0); issue(1); issue(2);

    float acc[4][4][4];
    #pragma unroll
    for (int a = 0; a < 4; a++)
        #pragma unroll
        for (int c = 0; c < 4; c++)
            #pragma unroll
            for (int d = 0; d < 4; d++) acc[a][c][d] = 0.0f;

    // ldmatrix lane addressing (constant per lane)
    const int a_krow = (lane & 7) + ((lane & 16) >> 1);
    const int a_moff = warp_m * 64 + (lane & 8);
    const int b_krow = (lane & 7) + (lane & 8);
    const int b_noff = warp_n * 32 + ((lane & 16) >> 1);

    for (int st = 0; st < NSTG; st++) {
        if (st <= NSTG - 3)      asm volatile("cp.async.wait_group 2;" ::: "memory");
        else if (st == NSTG - 2) asm volatile("cp.async.wait_group 1;" ::: "memory");
        else                     asm volatile("cp.async.wait_group 0;" ::: "memory");
        __syncthreads();
        // Writer slot (st+3)&3 != reader slot st&3 with STG=4: no aliasing.
        if (st + 3 < NSTG) issue(st + 3);

        const int slot = st & (STG - 1);
        const uint32_t a_base = Abase + slot * ASTG;
        const uint32_t b_base = Bbase + slot * BSTG;

        // per-k16-slice fragment load + mma (keeps regs <= 124 for 2 CTAs/SM)
        #pragma unroll
        for (int sl = 0; sl < 2; sl++) {
            uint32_t afr[4][4];
            uint32_t bfr[4][2];
            #pragma unroll
            for (int mi = 0; mi < 4; mi++) {
                uint32_t addr = a_base +
                    (uint32_t)(((sl * 16 + a_krow) * PM + a_moff + mi * 16) * 2);
                ldsm4t(afr[mi][0], afr[mi][1], afr[mi][2], afr[mi][3], addr);
            }
            #pragma unroll
            for (int q = 0; q < 2; q++) {
                uint32_t addr = b_base +
                    (uint32_t)(((sl * 16 + b_krow) * PN + b_noff + q * 16) * 2);
                ldsm4t(bfr[2*q][0], bfr[2*q][1], bfr[2*q+1][0], bfr[2*q+1][1], addr);
            }
            #pragma unroll
            for (int mi = 0; mi < 4; mi++)
                #pragma unroll
                for (int ni = 0; ni < 4; ni++)
                    mma16816(acc[mi][ni],
                             afr[mi][0], afr[mi][1], afr[mi][2], afr[mi][3],
                             bfr[ni][0], bfr[ni][1]);
        }
    }

    // ---- epilogue: bias + GELU + row-mean partial reduction ----
    const int group = lane >> 2;
    const int tid4  = lane & 3;

    float bcol[8];
    #pragma unroll
    for (int j = 0; j < 8; j++) {
        int ni = j >> 1, bs = j & 1;
        bcol[j] = bias[n0 + warp_n * 32 + ni * 8 + tid4 * 2 + bs];
    }

    float csum[8];
    #pragma unroll
    for (int j = 0; j < 8; j++) csum[j] = 0.0f;

    #pragma unroll
    for (int mi = 0; mi < 4; mi++) {
        #pragma unroll
        for (int half = 0; half < 2; half++) {
            int ow = warp_m * 64 + mi * 16 + half * 8 + group;
            bool ok = (ow < OW);
            #pragma unroll
            for (int ni = 0; ni < 4; ni++) {
                #pragma unroll
                for (int bs = 0; bs < 2; bs++) {
                    if (ok) {
                        float y = acc[mi][ni][half * 2 + bs] + bcol[ni * 2 + bs];
                        csum[ni * 2 + bs] += gelu_tanh(y);
                    }
                }
            }
        }
    }

    // reduce over the 8 lane-groups holding the same columns
    #pragma unroll
    for (int j = 0; j < 8; j++) {
        csum[j] += __shfl_xor_sync(0xffffffffu, csum[j], 16);
        csum[j] += __shfl_xor_sync(0xffffffffu, csum[j], 8);
        csum[j] += __shfl_xor_sync(0xffffffffu, csum[j], 4);
    }

    if (lane < 4) {
        const float inv = 1.0f / (float)MTOT;
        #pragma unroll
        for (int j = 0; j < 8; j++) {
            int ni = j >> 1, bs = j & 1;
            int n = n0 + warp_n * 32 + ni * 8 + tid4 * 2 + bs;
            atomicAdd(&out[b * COUT + n], csum[j] * inv);
        }
    }
}

// ---------------- launch ----------------

#define DSMEM_BYTES (STG * (ASTG + BSTG))   // 69632

extern "C" void kernel_launch(void* const* d_in, const int* in_sizes, int n_in,
                              void* d_out, int out_size) {
    const float* x    = (const float*)d_in[0];   // [64,64,128,128]
    const float* w    = (const float*)d_in[1];   // [256,64,3,3]
    const float* bias = (const float*)d_in[2];   // [256]
    float* out = (float*)d_out;                  // [64,256]

    cudaFuncSetAttribute(conv_gemm_kernel,
                         cudaFuncAttributeMaxDynamicSharedMemorySize, DSMEM_BYTES);

    // 1) x -> bf16, three kw-shifted aligned copies
    cvt_x3_kernel<<<32768, 256>>>(x);
    // 2) weights -> bf16, K-reordered [k'][co]
    cvt_w_kernel<<<KTOT, COUT>>>(w);
    // 3) zero output accumulator
    zero_kernel<<<(BATCH * COUT) / 256, 256>>>(out);
    // 4) fused implicit-GEMM conv + bias + GELU + mean-pool
    dim3 grid(OH, 2, BATCH);    // (126, 2 n-halves, 64)
    conv_gemm_kernel<<<grid, 256, DSMEM_BYTES>>>(bias, out);
}

// round 10
// speedup vs baseline: 1.2961x; 1.1117x over previous
#include <cuda_runtime.h>
#include <cuda_bf16.h>
#include <cstdint>

// Problem constants
#define BATCH 64
#define CIN   64
#define H     128
#define W     128
#define HW    (H*W)
#define COUT  256
#define OH    126
#define OW    126
#define MTOT  (OH*OW)     // 15876
#define KTOT  (CIN*9)     // 576
#define NSTG  9           // 9 stages of K=64 (one per (kh,kw))

static const size_t XN = (size_t)BATCH * CIN * H * W;   // 67,108,864

// Scratch (__device__ globals: allocation-free per harness rules)
// Three copies of x in bf16, shifted left by 0/1/2 elements (kw shift baked in)
__device__ __align__(16) __nv_bfloat16 g_xs[3][(size_t)BATCH*CIN*H*W + 64];
// Weights transposed + K-reordered: g_wbf[k'][co], k' = (kh*3+kw)*64 + ci
__device__ __align__(16) __nv_bfloat16 g_wbf[KTOT*COUT];

// ---------------- prologue kernels ----------------

__device__ __forceinline__ uint32_t packbf(float lo, float hi) {
    __nv_bfloat162 h = __floats2bfloat162_rn(lo, hi);
    return *reinterpret_cast<uint32_t*>(&h);
}

__global__ void cvt_x3_kernel(const float* __restrict__ x) {
    size_t p = ((size_t)blockIdx.x * blockDim.x + threadIdx.x) * 8;
    float4 a = *reinterpret_cast<const float4*>(x + p);
    float4 b = *reinterpret_cast<const float4*>(x + p + 4);
    float cx = 0.f, cy = 0.f;
    if (p + 8 < XN) cx = x[p + 8];
    if (p + 9 < XN) cy = x[p + 9];
    uint32_t r0 = packbf(a.x, a.y);
    uint32_t r1 = packbf(a.z, a.w);
    uint32_t r2 = packbf(b.x, b.y);
    uint32_t r3 = packbf(b.z, b.w);
    uint32_t r4 = packbf(cx, cy);
    *reinterpret_cast<uint4*>(&g_xs[0][p]) = make_uint4(r0, r1, r2, r3);
    uint32_t v0 = __funnelshift_r(r0, r1, 16);
    uint32_t v1 = __funnelshift_r(r1, r2, 16);
    uint32_t v2 = __funnelshift_r(r2, r3, 16);
    uint32_t v3 = __funnelshift_r(r3, r4, 16);
    *reinterpret_cast<uint4*>(&g_xs[1][p]) = make_uint4(v0, v1, v2, v3);
    *reinterpret_cast<uint4*>(&g_xs[2][p]) = make_uint4(r1, r2, r3, r4);
}

__global__ void cvt_w_kernel(const float* __restrict__ w) {
    // k' = khw*64 + ci ; original k = ci*9 + khw
    int kp = blockIdx.x;       // 0..575
    int n  = threadIdx.x;      // 0..255
    int ci  = kp & 63;
    int khw = kp >> 6;
    g_wbf[kp * COUT + n] = __float2bfloat16(w[n * KTOT + ci * 9 + khw]);
}

__global__ void zero_kernel(float* out) {
    out[blockIdx.x * blockDim.x + threadIdx.x] = 0.0f;
}

// ---------------- main implicit-GEMM kernel ----------------
// CTA tile: M128 (one oh row) x N128 (half of COUT); 8 warps, warp tile 64x32.
// K=64 stages (one (kh,kw) each), fully unrolled; STG=3 ring; 2 CTAs per SM.

#define PM 136     // A smem pitch (272B rows, conflict-free trans ldmatrix)
#define PN 136     // B smem pitch (N=128 tile)
#define STG 3
#define ASTG (64 * PM * 2)   // 17408 B per K64 stage
#define BSTG (64 * PN * 2)   // 17408 B per K64 stage

__device__ __forceinline__ uint32_t smem_u32(const void* p) {
    return (uint32_t)__cvta_generic_to_shared(p);
}

__device__ __forceinline__ void cp16(uint32_t dst, const void* src) {
    asm volatile("cp.async.cg.shared.global [%0], [%1], 16;\n" :: "r"(dst), "l"(src));
}

__device__ __forceinline__ void ldsm4t(uint32_t& r0, uint32_t& r1, uint32_t& r2,
                                       uint32_t& r3, uint32_t addr) {
    asm volatile("ldmatrix.sync.aligned.m8n8.x4.trans.shared.b16 {%0,%1,%2,%3}, [%4];"
                 : "=r"(r0), "=r"(r1), "=r"(r2), "=r"(r3) : "r"(addr));
}

__device__ __forceinline__ void mma16816(float c[4],
                                         uint32_t a0, uint32_t a1, uint32_t a2, uint32_t a3,
                                         uint32_t b0, uint32_t b1) {
    asm volatile("mma.sync.aligned.m16n8k16.row.col.f32.bf16.bf16.f32 "
                 "{%0,%1,%2,%3}, {%4,%5,%6,%7}, {%8,%9}, {%0,%1,%2,%3};"
                 : "+f"(c[0]), "+f"(c[1]), "+f"(c[2]), "+f"(c[3])
                 : "r"(a0), "r"(a1), "r"(a2), "r"(a3), "r"(b0), "r"(b1));
}

__device__ __forceinline__ float gelu_tanh(float x) {
    float x3 = x * x * x;
    float u = 0.7978845608028654f * fmaf(0.044715f, x3, x);
    float t;
    asm("tanh.approx.f32 %0, %1;" : "=f"(t) : "f"(u));
    return 0.5f * x * (1.0f + t);
}

__global__ void __launch_bounds__(256, 2)
conv_gemm_kernel(const float* __restrict__ bias, float* __restrict__ out) {
    extern __shared__ char dsm[];
    // Layout: A stages [STG][64*PM], then B stages [STG][64*PN]
    const uint32_t Abase = smem_u32(dsm);
    const uint32_t Bbase = Abase + STG * ASTG;

    const int tid    = threadIdx.x;
    const int lane   = tid & 31;
    const int warp   = tid >> 5;
    const int warp_m = warp >> 2;    // 0..1 -> 64 m-rows each
    const int warp_n = warp & 3;     // 0..3 -> 32 n-cols each
    const int oh = blockIdx.x;       // one output row per CTA
    const int n0 = blockIdx.y * 128; // COUT half
    const int b  = blockIdx.z;

    // staging roles: per 16-k-row shot, 16 rows x 16 chunks of 16B; 1 cp16/thread
    const int sk = tid >> 4, sj = tid & 15;

    const size_t xrow = ((size_t)(b * CIN)) * HW + (size_t)oh * W;
    const __nv_bfloat16* wsrc = g_wbf + n0 + sj * 8;   // + k'*COUT
    const uint32_t a_sdst = Abase + (sk * PM + sj * 8) * 2;
    const uint32_t b_sdst = Bbase + (sk * PN + sj * 8) * 2;

    // --- pipeline issue: one stage = K64 = one (kh,kw), ci 0..63 ---
    auto issue = [&](int st) {
        const int slot = st % STG;
        const int kh = (st * 11) >> 5;     // floor(st/3), st in [0,9)
        const int kw = st - kh * 3;
        const __nv_bfloat16* abase = g_xs[kw] + xrow + (size_t)kh * W + sj * 8;
        #pragma unroll
        for (int i = 0; i < 4; i++) {      // shots: ci rows 16i+sk
            cp16(a_sdst + slot * ASTG + i * (16 * PM * 2),
                 abase + (size_t)(i * 16 + sk) * HW);
            cp16(b_sdst + slot * BSTG + i * (16 * PN * 2),
                 wsrc + (size_t)(st * 64 + i * 16 + sk) * COUT);
        }
        asm volatile("cp.async.commit_group;" ::: "memory");
    };

    issue(0); issue(1);

    float acc[4][4][4];
    #pragma unroll
    for (int a = 0; a < 4; a++)
        #pragma unroll
        for (int c = 0; c < 4; c++)
            #pragma unroll
            for (int d = 0; d < 4; d++) acc[a][c][d] = 0.0f;

    // ldmatrix lane addressing (constant per lane)
    const int a_krow = (lane & 7) + ((lane & 16) >> 1);
    const int a_moff = warp_m * 64 + (lane & 8);
    const int b_krow = (lane & 7) + (lane & 8);
    const int b_noff = warp_n * 32 + ((lane & 16) >> 1);

    #pragma unroll
    for (int st = 0; st < NSTG; st++) {
        if (st < NSTG - 2) asm volatile("cp.async.wait_group 1;" ::: "memory");
        else               asm volatile("cp.async.wait_group 0;" ::: "memory");
        __syncthreads();
        // Writer slot (st+2)%3 != reader slot st%3: no aliasing.
        if (st + 2 < NSTG) issue(st + 2);

        const int slot = st % STG;
        const uint32_t a_base = Abase + slot * ASTG;
        const uint32_t b_base = Bbase + slot * BSTG;

        // 4 k16 slices per stage; per-slice scoping keeps regs <= 124
        #pragma unroll
        for (int sl = 0; sl < 4; sl++) {
            uint32_t afr[4][4];
            uint32_t bfr[4][2];
            #pragma unroll
            for (int mi = 0; mi < 4; mi++) {
                uint32_t addr = a_base +
                    (uint32_t)(((sl * 16 + a_krow) * PM + a_moff + mi * 16) * 2);
                ldsm4t(afr[mi][0], afr[mi][1], afr[mi][2], afr[mi][3], addr);
            }
            #pragma unroll
            for (int q = 0; q < 2; q++) {
                uint32_t addr = b_base +
                    (uint32_t)(((sl * 16 + b_krow) * PN + b_noff + q * 16) * 2);
                ldsm4t(bfr[2*q][0], bfr[2*q][1], bfr[2*q+1][0], bfr[2*q+1][1], addr);
            }
            #pragma unroll
            for (int mi = 0; mi < 4; mi++)
                #pragma unroll
                for (int ni = 0; ni < 4; ni++)
                    mma16816(acc[mi][ni],
                             afr[mi][0], afr[mi][1], afr[mi][2], afr[mi][3],
                             bfr[ni][0], bfr[ni][1]);
        }
    }

    // ---- epilogue: bias + GELU + row-mean partial reduction ----
    const int group = lane >> 2;
    const int tid4  = lane & 3;

    float bcol[8];
    #pragma unroll
    for (int j = 0; j < 8; j++) {
        int ni = j >> 1, bs = j & 1;
        bcol[j] = bias[n0 + warp_n * 32 + ni * 8 + tid4 * 2 + bs];
    }

    float csum[8];
    #pragma unroll
    for (int j = 0; j < 8; j++) csum[j] = 0.0f;

    #pragma unroll
    for (int mi = 0; mi < 4; mi++) {
        #pragma unroll
        for (int half = 0; half < 2; half++) {
            int ow = warp_m * 64 + mi * 16 + half * 8 + group;
            bool ok = (ow < OW);
            #pragma unroll
            for (int ni = 0; ni < 4; ni++) {
                #pragma unroll
                for (int bs = 0; bs < 2; bs++) {
                    if (ok) {
                        float y = acc[mi][ni][half * 2 + bs] + bcol[ni * 2 + bs];
                        csum[ni * 2 + bs] += gelu_tanh(y);
                    }
                }
            }
        }
    }

    // reduce over the 8 lane-groups holding the same columns
    #pragma unroll
    for (int j = 0; j < 8; j++) {
        csum[j] += __shfl_xor_sync(0xffffffffu, csum[j], 16);
        csum[j] += __shfl_xor_sync(0xffffffffu, csum[j], 8);
        csum[j] += __shfl_xor_sync(0xffffffffu, csum[j], 4);
    }

    if (lane < 4) {
        const float inv = 1.0f / (float)MTOT;
        #pragma unroll
        for (int j = 0; j < 8; j++) {
            int ni = j >> 1, bs = j & 1;
            int n = n0 + warp_n * 32 + ni * 8 + tid4 * 2 + bs;
            atomicAdd(&out[b * COUT + n], csum[j] * inv);
        }
    }
}

// ---------------- launch ----------------

#define DSMEM_BYTES (STG * (ASTG + BSTG))   // 104448

extern "C" void kernel_launch(void* const* d_in, const int* in_sizes, int n_in,
                              void* d_out, int out_size) {
    const float* x    = (const float*)d_in[0];   // [64,64,128,128]
    const float* w    = (const float*)d_in[1];   // [256,64,3,3]
    const float* bias = (const float*)d_in[2];   // [256]
    float* out = (float*)d_out;                  // [64,256]

    cudaFuncSetAttribute(conv_gemm_kernel,
                         cudaFuncAttributeMaxDynamicSharedMemorySize, DSMEM_BYTES);

    // 1) x -> bf16, three kw-shifted aligned copies
    cvt_x3_kernel<<<32768, 256>>>(x);
    // 2) weights -> bf16, K-reordered [k'][co]
    cvt_w_kernel<<<KTOT, COUT>>>(w);
    // 3) zero output accumulator
    zero_kernel<<<(BATCH * COUT) / 256, 256>>>(out);
    // 4) fused implicit-GEMM conv + bias + GELU + mean-pool
    dim3 grid(OH, 2, BATCH);    // (126, 2 n-halves, 64)
    conv_gemm_kernel<<<grid, 256, DSMEM_BYTES>>>(bias, out);
}

// round 11
// speedup vs baseline: 1.3169x; 1.0160x over previous
#include <cuda_runtime.h>
#include <cuda_bf16.h>
#include <cstdint>

// Problem constants
#define BATCH 64
#define CIN   64
#define H     128
#define W     128
#define HW    (H*W)
#define COUT  256
#define OH    126
#define OW    126
#define MTOT  (OH*OW)     // 15876
#define KTOT  (CIN*9)     // 576
#define NSTG  9           // 9 stages of K=64 (one per (kh,kw))

static const size_t XN = (size_t)BATCH * CIN * H * W;   // 67,108,864

// Scratch (__device__ globals: allocation-free per harness rules)
// Three copies of x in bf16, shifted left by 0/1/2 elements (kw shift baked in)
__device__ __align__(16) __nv_bfloat16 g_xs[3][(size_t)BATCH*CIN*H*W + 64];
// Weights transposed + K-reordered: g_wbf[k'][co], k' = (kh*3+kw)*64 + ci
__device__ __align__(16) __nv_bfloat16 g_wbf[KTOT*COUT];

// ---------------- prologue kernels ----------------

__device__ __forceinline__ uint32_t packbf(float lo, float hi) {
    __nv_bfloat162 h = __floats2bfloat162_rn(lo, hi);
    return *reinterpret_cast<uint32_t*>(&h);
}

__global__ void cvt_x3_kernel(const float* __restrict__ x) {
    size_t p = ((size_t)blockIdx.x * blockDim.x + threadIdx.x) * 8;
    float4 a = *reinterpret_cast<const float4*>(x + p);
    float4 b = *reinterpret_cast<const float4*>(x + p + 4);
    float cx = 0.f, cy = 0.f;
    if (p + 8 < XN) cx = x[p + 8];
    if (p + 9 < XN) cy = x[p + 9];
    uint32_t r0 = packbf(a.x, a.y);
    uint32_t r1 = packbf(a.z, a.w);
    uint32_t r2 = packbf(b.x, b.y);
    uint32_t r3 = packbf(b.z, b.w);
    uint32_t r4 = packbf(cx, cy);
    *reinterpret_cast<uint4*>(&g_xs[0][p]) = make_uint4(r0, r1, r2, r3);
    uint32_t v0 = __funnelshift_r(r0, r1, 16);
    uint32_t v1 = __funnelshift_r(r1, r2, 16);
    uint32_t v2 = __funnelshift_r(r2, r3, 16);
    uint32_t v3 = __funnelshift_r(r3, r4, 16);
    *reinterpret_cast<uint4*>(&g_xs[1][p]) = make_uint4(v0, v1, v2, v3);
    *reinterpret_cast<uint4*>(&g_xs[2][p]) = make_uint4(r1, r2, r3, r4);
}

// weights reorder + output zero in one launch
__global__ void cvt_w_zero_kernel(const float* __restrict__ w, float* __restrict__ out) {
    int kp = blockIdx.x;       // 0..575
    int n  = threadIdx.x;      // 0..255
    int ci  = kp & 63;
    int khw = kp >> 6;
    g_wbf[kp * COUT + n] = __float2bfloat16(w[n * KTOT + ci * 9 + khw]);
    if (kp < 64) out[kp * COUT + n] = 0.0f;    // 64*256 = BATCH*COUT
}

// ---------------- main implicit-GEMM kernel ----------------
// CTA tile: M128 (one oh row) x N128 (half of COUT); 8 warps, warp tile 64x32.
// K=64 stages (one (kh,kw) each), fully unrolled; STG=3 ring; 2 CTAs per SM.
// Fragments double-buffered across k16 slices: ldsm(sl+1) issued before mma(sl).

#define PM 136     // A smem pitch (272B rows, conflict-free trans ldmatrix)
#define PN 136     // B smem pitch (N=128 tile)
#define STG 3
#define ASTG (64 * PM * 2)   // 17408 B per K64 stage
#define BSTG (64 * PN * 2)   // 17408 B per K64 stage

__device__ __forceinline__ uint32_t smem_u32(const void* p) {
    return (uint32_t)__cvta_generic_to_shared(p);
}

__device__ __forceinline__ void cp16(uint32_t dst, const void* src) {
    asm volatile("cp.async.cg.shared.global [%0], [%1], 16;\n" :: "r"(dst), "l"(src));
}

__device__ __forceinline__ void ldsm4t(uint32_t& r0, uint32_t& r1, uint32_t& r2,
                                       uint32_t& r3, uint32_t addr) {
    asm volatile("ldmatrix.sync.aligned.m8n8.x4.trans.shared.b16 {%0,%1,%2,%3}, [%4];"
                 : "=r"(r0), "=r"(r1), "=r"(r2), "=r"(r3) : "r"(addr));
}

__device__ __forceinline__ void mma16816(float c[4],
                                         uint32_t a0, uint32_t a1, uint32_t a2, uint32_t a3,
                                         uint32_t b0, uint32_t b1) {
    asm volatile("mma.sync.aligned.m16n8k16.row.col.f32.bf16.bf16.f32 "
                 "{%0,%1,%2,%3}, {%4,%5,%6,%7}, {%8,%9}, {%0,%1,%2,%3};"
                 : "+f"(c[0]), "+f"(c[1]), "+f"(c[2]), "+f"(c[3])
                 : "r"(a0), "r"(a1), "r"(a2), "r"(a3), "r"(b0), "r"(b1));
}

__device__ __forceinline__ float gelu_tanh(float x) {
    float x3 = x * x * x;
    float u = 0.7978845608028654f * fmaf(0.044715f, x3, x);
    float t;
    asm("tanh.approx.f32 %0, %1;" : "=f"(t) : "f"(u));
    return 0.5f * x * (1.0f + t);
}

__global__ void __launch_bounds__(256, 2)
conv_gemm_kernel(const float* __restrict__ bias, float* __restrict__ out) {
    extern __shared__ char dsm[];
    // Layout: A stages [STG][64*PM], then B stages [STG][64*PN]
    const uint32_t Abase = smem_u32(dsm);
    const uint32_t Bbase = Abase + STG * ASTG;

    const int tid    = threadIdx.x;
    const int lane   = tid & 31;
    const int warp   = tid >> 5;
    const int warp_m = warp >> 2;    // 0..1 -> 64 m-rows each
    const int warp_n = warp & 3;     // 0..3 -> 32 n-cols each
    const int oh = blockIdx.x;       // one output row per CTA
    const int n0 = blockIdx.y * 128; // COUT half
    const int b  = blockIdx.z;

    // staging roles: per 16-k-row shot, 16 rows x 16 chunks of 16B; 1 cp16/thread
    const int sk = tid >> 4, sj = tid & 15;

    const size_t xrow = ((size_t)(b * CIN)) * HW + (size_t)oh * W;
    const __nv_bfloat16* wsrc = g_wbf + n0 + sj * 8;   // + k'*COUT
    const uint32_t a_sdst = Abase + (sk * PM + sj * 8) * 2;
    const uint32_t b_sdst = Bbase + (sk * PN + sj * 8) * 2;

    // --- pipeline issue: one stage = K64 = one (kh,kw), ci 0..63 ---
    auto issue = [&](int st) {
        const int slot = st % STG;
        const int kh = (st * 11) >> 5;     // floor(st/3), st in [0,9)
        const int kw = st - kh * 3;
        const __nv_bfloat16* abase = g_xs[kw] + xrow + (size_t)kh * W + sj * 8;
        #pragma unroll
        for (int i = 0; i < 4; i++) {      // shots: ci rows 16i+sk
            cp16(a_sdst + slot * ASTG + i * (16 * PM * 2),
                 abase + (size_t)(i * 16 + sk) * HW);
            cp16(b_sdst + slot * BSTG + i * (16 * PN * 2),
                 wsrc + (size_t)(st * 64 + i * 16 + sk) * COUT);
        }
        asm volatile("cp.async.commit_group;" ::: "memory");
    };

    issue(0); issue(1);

    float acc[4][4][4];
    #pragma unroll
    for (int a = 0; a < 4; a++)
        #pragma unroll
        for (int c = 0; c < 4; c++)
            #pragma unroll
            for (int d = 0; d < 4; d++) acc[a][c][d] = 0.0f;

    // ldmatrix lane addressing (constant per lane)
    const int a_krow = (lane & 7) + ((lane & 16) >> 1);
    const int a_moff = warp_m * 64 + (lane & 8);
    const int b_krow = (lane & 7) + (lane & 8);
    const int b_noff = warp_n * 32 + ((lane & 16) >> 1);

    // double-buffered fragments (2 x 24 regs)
    uint32_t afr[2][4][4];
    uint32_t bfr[2][4][2];

    #pragma unroll
    for (int st = 0; st < NSTG; st++) {
        if (st < NSTG - 2) asm volatile("cp.async.wait_group 1;" ::: "memory");
        else               asm volatile("cp.async.wait_group 0;" ::: "memory");
        __syncthreads();

        const int slot = st % STG;
        const uint32_t a_base = Abase + slot * ASTG;
        const uint32_t b_base = Bbase + slot * BSTG;

        // slice-0 fragments FIRST (tensor pipe restarts ASAP) ...
        #pragma unroll
        for (int mi = 0; mi < 4; mi++) {
            uint32_t addr = a_base + (uint32_t)(((a_krow) * PM + a_moff + mi * 16) * 2);
            ldsm4t(afr[0][mi][0], afr[0][mi][1], afr[0][mi][2], afr[0][mi][3], addr);
        }
        #pragma unroll
        for (int q = 0; q < 2; q++) {
            uint32_t addr = b_base + (uint32_t)(((b_krow) * PN + b_noff + q * 16) * 2);
            ldsm4t(bfr[0][2*q][0], bfr[0][2*q][1], bfr[0][2*q+1][0], bfr[0][2*q+1][1], addr);
        }
        // ... then the non-urgent cp.async for stage st+2 (slot (st+2)%3 != st%3)
        if (st + 2 < NSTG) issue(st + 2);

        // pipelined slices: ldsm(sl+1) before mma(sl)
        #pragma unroll
        for (int sl = 0; sl < 4; sl++) {
            const int cur = sl & 1, nxt = cur ^ 1;
            if (sl < 3) {
                #pragma unroll
                for (int mi = 0; mi < 4; mi++) {
                    uint32_t addr = a_base +
                        (uint32_t)((((sl + 1) * 16 + a_krow) * PM + a_moff + mi * 16) * 2);
                    ldsm4t(afr[nxt][mi][0], afr[nxt][mi][1],
                           afr[nxt][mi][2], afr[nxt][mi][3], addr);
                }
                #pragma unroll
                for (int q = 0; q < 2; q++) {
                    uint32_t addr = b_base +
                        (uint32_t)((((sl + 1) * 16 + b_krow) * PN + b_noff + q * 16) * 2);
                    ldsm4t(bfr[nxt][2*q][0], bfr[nxt][2*q][1],
                           bfr[nxt][2*q+1][0], bfr[nxt][2*q+1][1], addr);
                }
            }
            #pragma unroll
            for (int mi = 0; mi < 4; mi++)
                #pragma unroll
                for (int ni = 0; ni < 4; ni++)
                    mma16816(acc[mi][ni],
                             afr[cur][mi][0], afr[cur][mi][1],
                             afr[cur][mi][2], afr[cur][mi][3],
                             bfr[cur][ni][0], bfr[cur][ni][1]);
        }
    }

    // ---- epilogue: bias + GELU + row-mean partial reduction ----
    const int group = lane >> 2;
    const int tid4  = lane & 3;

    float bcol[8];
    #pragma unroll
    for (int j = 0; j < 8; j++) {
        int ni = j >> 1, bs = j & 1;
        bcol[j] = bias[n0 + warp_n * 32 + ni * 8 + tid4 * 2 + bs];
    }

    float csum[8];
    #pragma unroll
    for (int j = 0; j < 8; j++) csum[j] = 0.0f;

    #pragma unroll
    for (int mi = 0; mi < 4; mi++) {
        #pragma unroll
        for (int half = 0; half < 2; half++) {
            int ow = warp_m * 64 + mi * 16 + half * 8 + group;
            bool ok = (ow < OW);
            #pragma unroll
            for (int ni = 0; ni < 4; ni++) {
                #pragma unroll
                for (int bs = 0; bs < 2; bs++) {
                    if (ok) {
                        float y = acc[mi][ni][half * 2 + bs] + bcol[ni * 2 + bs];
                        csum[ni * 2 + bs] += gelu_tanh(y);
                    }
                }
            }
        }
    }

    // reduce over the 8 lane-groups holding the same columns
    #pragma unroll
    for (int j = 0; j < 8; j++) {
        csum[j] += __shfl_xor_sync(0xffffffffu, csum[j], 16);
        csum[j] += __shfl_xor_sync(0xffffffffu, csum[j], 8);
        csum[j] += __shfl_xor_sync(0xffffffffu, csum[j], 4);
    }

    if (lane < 4) {
        const float inv = 1.0f / (float)MTOT;
        #pragma unroll
        for (int j = 0; j < 8; j++) {
            int ni = j >> 1, bs = j & 1;
            int n = n0 + warp_n * 32 + ni * 8 + tid4 * 2 + bs;
            atomicAdd(&out[b * COUT + n], csum[j] * inv);
        }
    }
}

// ---------------- launch ----------------

#define DSMEM_BYTES (STG * (ASTG + BSTG))   // 104448

extern "C" void kernel_launch(void* const* d_in, const int* in_sizes, int n_in,
                              void* d_out, int out_size) {
    const float* x    = (const float*)d_in[0];   // [64,64,128,128]
    const float* w    = (const float*)d_in[1];   // [256,64,3,3]
    const float* bias = (const float*)d_in[2];   // [256]
    float* out = (float*)d_out;                  // [64,256]

    cudaFuncSetAttribute(conv_gemm_kernel,
                         cudaFuncAttributeMaxDynamicSharedMemorySize, DSMEM_BYTES);

    // 1) x -> bf16, three kw-shifted aligned copies
    cvt_x3_kernel<<<32768, 256>>>(x);
    // 2) weights -> bf16 K-reordered [k'][co]; zero output accumulator
    cvt_w_zero_kernel<<<KTOT, COUT>>>(w, out);
    // 3) fused implicit-GEMM conv + bias + GELU + mean-pool
    dim3 grid(OH, 2, BATCH);    // (126, 2 n-halves, 64)
    conv_gemm_kernel<<<grid, 256, DSMEM_BYTES>>>(bias, out);
}

// round 12
// speedup vs baseline: 1.3563x; 1.0300x over previous
#include <cuda_runtime.h>
#include <cuda_bf16.h>
#include <cstdint>

// Problem constants
#define BATCH 64
#define CIN   64
#define H     128
#define W     128
#define HW    (H*W)
#define COUT  256
#define OH    126
#define OW    126
#define MTOT  (OH*OW)     // 15876
#define KTOT  (CIN*9)     // 576
#define NSTG  9           // 9 stages of K=64 (one per (kh,kw))

static const size_t XN = (size_t)BATCH * CIN * H * W;   // 67,108,864

// Scratch (__device__ globals: allocation-free per harness rules)
// Three copies of x in bf16, shifted left by 0/1/2 elements (kw shift baked in)
__device__ __align__(16) __nv_bfloat16 g_xs[3][(size_t)BATCH*CIN*H*W + 64];
// Weights transposed + K-reordered: g_wbf[k'][co], k' = (kh*3+kw)*64 + ci
__device__ __align__(16) __nv_bfloat16 g_wbf[KTOT*COUT];

// ---------------- prologue kernels ----------------

__device__ __forceinline__ uint32_t packbf(float lo, float hi) {
    __nv_bfloat162 h = __floats2bfloat162_rn(lo, hi);
    return *reinterpret_cast<uint32_t*>(&h);
}

__global__ void cvt_x3_kernel(const float* __restrict__ x) {
    size_t p = ((size_t)blockIdx.x * blockDim.x + threadIdx.x) * 8;
    float4 a = *reinterpret_cast<const float4*>(x + p);
    float4 b = *reinterpret_cast<const float4*>(x + p + 4);
    float cx = 0.f, cy = 0.f;
    if (p + 8 < XN) cx = x[p + 8];
    if (p + 9 < XN) cy = x[p + 9];
    uint32_t r0 = packbf(a.x, a.y);
    uint32_t r1 = packbf(a.z, a.w);
    uint32_t r2 = packbf(b.x, b.y);
    uint32_t r3 = packbf(b.z, b.w);
    uint32_t r4 = packbf(cx, cy);
    *reinterpret_cast<uint4*>(&g_xs[0][p]) = make_uint4(r0, r1, r2, r3);
    uint32_t v0 = __funnelshift_r(r0, r1, 16);
    uint32_t v1 = __funnelshift_r(r1, r2, 16);
    uint32_t v2 = __funnelshift_r(r2, r3, 16);
    uint32_t v3 = __funnelshift_r(r3, r4, 16);
    *reinterpret_cast<uint4*>(&g_xs[1][p]) = make_uint4(v0, v1, v2, v3);
    *reinterpret_cast<uint4*>(&g_xs[2][p]) = make_uint4(r1, r2, r3, r4);
}

// weights reorder + output zero in one launch
__global__ void cvt_w_zero_kernel(const float* __restrict__ w, float* __restrict__ out) {
    int kp = blockIdx.x;       // 0..575
    int n  = threadIdx.x;      // 0..255
    int ci  = kp & 63;
    int khw = kp >> 6;
    g_wbf[kp * COUT + n] = __float2bfloat16(w[n * KTOT + ci * 9 + khw]);
    if (kp < 64) out[kp * COUT + n] = 0.0f;    // 64*256 = BATCH*COUT
}

// ---------------- main implicit-GEMM kernel ----------------
// CTA tile: M128 (one oh row) x N128 (half of COUT); 4 warps, warp tile 64x64.
// K=64 stages (one (kh,kw) each), fully unrolled; STG=3 ring; 2 CTAs per SM.
// ldsm:mma ratio 8:32 per warp-slice (was 6:16) -> smem traffic -33%.

#define PM 136     // A smem pitch (272B rows, conflict-free trans ldmatrix)
#define PN 136     // B smem pitch (N=128 tile)
#define STG 3
#define ASTG (64 * PM * 2)   // 17408 B per K64 stage
#define BSTG (64 * PN * 2)   // 17408 B per K64 stage

__device__ __forceinline__ uint32_t smem_u32(const void* p) {
    return (uint32_t)__cvta_generic_to_shared(p);
}

__device__ __forceinline__ void cp16(uint32_t dst, const void* src) {
    asm volatile("cp.async.cg.shared.global [%0], [%1], 16;\n" :: "r"(dst), "l"(src));
}

__device__ __forceinline__ void ldsm4t(uint32_t& r0, uint32_t& r1, uint32_t& r2,
                                       uint32_t& r3, uint32_t addr) {
    asm volatile("ldmatrix.sync.aligned.m8n8.x4.trans.shared.b16 {%0,%1,%2,%3}, [%4];"
                 : "=r"(r0), "=r"(r1), "=r"(r2), "=r"(r3) : "r"(addr));
}

__device__ __forceinline__ void mma16816(float c[4],
                                         uint32_t a0, uint32_t a1, uint32_t a2, uint32_t a3,
                                         uint32_t b0, uint32_t b1) {
    asm volatile("mma.sync.aligned.m16n8k16.row.col.f32.bf16.bf16.f32 "
                 "{%0,%1,%2,%3}, {%4,%5,%6,%7}, {%8,%9}, {%0,%1,%2,%3};"
                 : "+f"(c[0]), "+f"(c[1]), "+f"(c[2]), "+f"(c[3])
                 : "r"(a0), "r"(a1), "r"(a2), "r"(a3), "r"(b0), "r"(b1));
}

__device__ __forceinline__ float gelu_tanh(float x) {
    float x3 = x * x * x;
    float u = 0.7978845608028654f * fmaf(0.044715f, x3, x);
    float t;
    asm("tanh.approx.f32 %0, %1;" : "=f"(t) : "f"(u));
    return 0.5f * x * (1.0f + t);
}

__global__ void __launch_bounds__(128, 2)
conv_gemm_kernel(const float* __restrict__ bias, float* __restrict__ out) {
    extern __shared__ char dsm[];
    // Layout: A stages [STG][64*PM], then B stages [STG][64*PN]
    const uint32_t Abase = smem_u32(dsm);
    const uint32_t Bbase = Abase + STG * ASTG;

    const int tid    = threadIdx.x;
    const int lane   = tid & 31;
    const int warp   = tid >> 5;     // 0..3
    const int warp_m = warp >> 1;    // 0..1 -> 64 m-rows each
    const int warp_n = warp & 1;     // 0..1 -> 64 n-cols each
    const int oh = blockIdx.x;       // one output row per CTA
    const int n0 = blockIdx.y * 128; // COUT half
    const int b  = blockIdx.z;

    // staging roles: thread handles k-rows (8i + sk), 16B chunk sj; 16 cp16/stage
    const int sk = tid >> 4, sj = tid & 15;

    const size_t xrow = ((size_t)(b * CIN)) * HW + (size_t)oh * W;
    const __nv_bfloat16* wsrc = g_wbf + n0 + sj * 8;   // + k'*COUT
    const uint32_t a_sdst = Abase + (sk * PM + sj * 8) * 2;
    const uint32_t b_sdst = Bbase + (sk * PN + sj * 8) * 2;

    // --- pipeline issue: one stage = K64 = one (kh,kw), ci 0..63 ---
    auto issue = [&](int st) {
        const int slot = st % STG;
        const int kh = (st * 11) >> 5;     // floor(st/3), st in [0,9)
        const int kw = st - kh * 3;
        const __nv_bfloat16* abase = g_xs[kw] + xrow + (size_t)kh * W + sj * 8;
        #pragma unroll
        for (int i = 0; i < 8; i++) {      // k-rows 8i + sk
            cp16(a_sdst + slot * ASTG + i * (8 * PM * 2),
                 abase + (size_t)(i * 8 + sk) * HW);
            cp16(b_sdst + slot * BSTG + i * (8 * PN * 2),
                 wsrc + (size_t)(st * 64 + i * 8 + sk) * COUT);
        }
        asm volatile("cp.async.commit_group;" ::: "memory");
    };

    issue(0); issue(1);

    float acc[4][8][4];
    #pragma unroll
    for (int a = 0; a < 4; a++)
        #pragma unroll
        for (int c = 0; c < 8; c++)
            #pragma unroll
            for (int d = 0; d < 4; d++) acc[a][c][d] = 0.0f;

    // ldmatrix lane addressing (constant per lane)
    const int a_krow = (lane & 7) + ((lane & 16) >> 1);
    const int a_moff = warp_m * 64 + (lane & 8);
    const int b_krow = (lane & 7) + (lane & 8);
    const int b_noff = warp_n * 64 + ((lane & 16) >> 1);

    // double-buffered fragments (2 x 32 regs)
    uint32_t afr[2][4][4];
    uint32_t bfr[2][8][2];

    #pragma unroll
    for (int st = 0; st < NSTG; st++) {
        if (st < NSTG - 2) asm volatile("cp.async.wait_group 1;" ::: "memory");
        else               asm volatile("cp.async.wait_group 0;" ::: "memory");
        __syncthreads();

        const int slot = st % STG;
        const uint32_t a_base = Abase + slot * ASTG;
        const uint32_t b_base = Bbase + slot * BSTG;

        // slice-0 fragments FIRST (tensor pipe restarts ASAP) ...
        #pragma unroll
        for (int mi = 0; mi < 4; mi++) {
            uint32_t addr = a_base + (uint32_t)((a_krow * PM + a_moff + mi * 16) * 2);
            ldsm4t(afr[0][mi][0], afr[0][mi][1], afr[0][mi][2], afr[0][mi][3], addr);
        }
        #pragma unroll
        for (int q = 0; q < 4; q++) {
            uint32_t addr = b_base + (uint32_t)((b_krow * PN + b_noff + q * 16) * 2);
            ldsm4t(bfr[0][2*q][0], bfr[0][2*q][1], bfr[0][2*q+1][0], bfr[0][2*q+1][1], addr);
        }
        // ... then the non-urgent cp.async for stage st+2 (slot (st+2)%3 != st%3)
        if (st + 2 < NSTG) issue(st + 2);

        // pipelined slices: ldsm(sl+1) before mma(sl)
        #pragma unroll
        for (int sl = 0; sl < 4; sl++) {
            const int cur = sl & 1, nxt = cur ^ 1;
            if (sl < 3) {
                #pragma unroll
                for (int mi = 0; mi < 4; mi++) {
                    uint32_t addr = a_base +
                        (uint32_t)((((sl + 1) * 16 + a_krow) * PM + a_moff + mi * 16) * 2);
                    ldsm4t(afr[nxt][mi][0], afr[nxt][mi][1],
                           afr[nxt][mi][2], afr[nxt][mi][3], addr);
                }
                #pragma unroll
                for (int q = 0; q < 4; q++) {
                    uint32_t addr = b_base +
                        (uint32_t)((((sl + 1) * 16 + b_krow) * PN + b_noff + q * 16) * 2);
                    ldsm4t(bfr[nxt][2*q][0], bfr[nxt][2*q][1],
                           bfr[nxt][2*q+1][0], bfr[nxt][2*q+1][1], addr);
                }
            }
            #pragma unroll
            for (int mi = 0; mi < 4; mi++)
                #pragma unroll
                for (int ni = 0; ni < 8; ni++)
                    mma16816(acc[mi][ni],
                             afr[cur][mi][0], afr[cur][mi][1],
                             afr[cur][mi][2], afr[cur][mi][3],
                             bfr[cur][ni][0], bfr[cur][ni][1]);
        }
    }

    // ---- epilogue: bias + GELU + row-mean partial reduction ----
    const int group = lane >> 2;
    const int tid4  = lane & 3;

    float bcol[16];
    #pragma unroll
    for (int j = 0; j < 16; j++) {
        int ni = j >> 1, bs = j & 1;
        bcol[j] = bias[n0 + warp_n * 64 + ni * 8 + tid4 * 2 + bs];
    }

    float csum[16];
    #pragma unroll
    for (int j = 0; j < 16; j++) csum[j] = 0.0f;

    #pragma unroll
    for (int mi = 0; mi < 4; mi++) {
        #pragma unroll
        for (int half = 0; half < 2; half++) {
            int ow = warp_m * 64 + mi * 16 + half * 8 + group;
            bool ok = (ow < OW);
            #pragma unroll
            for (int ni = 0; ni < 8; ni++) {
                #pragma unroll
                for (int bs = 0; bs < 2; bs++) {
                    if (ok) {
                        float y = acc[mi][ni][half * 2 + bs] + bcol[ni * 2 + bs];
                        csum[ni * 2 + bs] += gelu_tanh(y);
                    }
                }
            }
        }
    }

    // reduce over the 8 lane-groups holding the same columns
    #pragma unroll
    for (int j = 0; j < 16; j++) {
        csum[j] += __shfl_xor_sync(0xffffffffu, csum[j], 16);
        csum[j] += __shfl_xor_sync(0xffffffffu, csum[j], 8);
        csum[j] += __shfl_xor_sync(0xffffffffu, csum[j], 4);
    }

    if (lane < 4) {
        const float inv = 1.0f / (float)MTOT;
        #pragma unroll
        for (int j = 0; j < 16; j++) {
            int ni = j >> 1, bs = j & 1;
            int n = n0 + warp_n * 64 + ni * 8 + tid4 * 2 + bs;
            atomicAdd(&out[b * COUT + n], csum[j] * inv);
        }
    }
}

// ---------------- launch ----------------

#define DSMEM_BYTES (STG * (ASTG + BSTG))   // 104448

extern "C" void kernel_launch(void* const* d_in, const int* in_sizes, int n_in,
                              void* d_out, int out_size) {
    const float* x    = (const float*)d_in[0];   // [64,64,128,128]
    const float* w    = (const float*)d_in[1];   // [256,64,3,3]
    const float* bias = (const float*)d_in[2];   // [256]
    float* out = (float*)d_out;                  // [64,256]

    cudaFuncSetAttribute(conv_gemm_kernel,
                         cudaFuncAttributeMaxDynamicSharedMemorySize, DSMEM_BYTES);

    // 1) x -> bf16, three kw-shifted aligned copies
    cvt_x3_kernel<<<32768, 256>>>(x);
    // 2) weights -> bf16 K-reordered [k'][co]; zero output accumulator
    cvt_w_zero_kernel<<<KTOT, COUT>>>(w, out);
    // 3) fused implicit-GEMM conv + bias + GELU + mean-pool
    dim3 grid(OH, 2, BATCH);    // (126, 2 n-halves, 64)
    conv_gemm_kernel<<<grid, 128, DSMEM_BYTES>>>(bias, out);
}